// round 1
// baseline (speedup 1.0000x reference)
#include <cuda_runtime.h>
#include <cstdint>

// Problem constants
#define Bn 8
#define Cn 16
#define Ln 512
#define Dn 256
#define Mrows (Bn*Ln*Cn)     // 65536
#define Ncols 768            // q | k' | u  (u = v @ Wout^T path, combined)
#define Kdim 256

// Scratch (device globals; no runtime allocation allowed)
__device__ float g_W3[Ncols * Kdim];      // 768x256 combined weight (K-major rows)
__device__ float g_b3[Ncols];             // combined bias
__device__ float g_Y[(size_t)Mrows * Ncols]; // 192 MB intermediate

__device__ __forceinline__ float fast_tanh(float x) {
    float y;
    asm("tanh.approx.f32 %0, %1;" : "=f"(y) : "f"(x));
    return y;
}

// ---------------------------------------------------------------------------
// Kernel 1: build combined weights.
//   rows [0,256)   : Wq,            bias bq
//   rows [256,512) : Wk,            bias bk + bh   (fold bh into k)
//   rows [512,768) : Wout @ Wv,     bias Wout @ bv (output proj folded into v)
// ---------------------------------------------------------------------------
__global__ void prep_kernel(const float* __restrict__ Wqkv,
                            const float* __restrict__ bqkv,
                            const float* __restrict__ bh,
                            const float* __restrict__ Wout) {
    __shared__ float ws[256];
    int i = blockIdx.x;      // output row of W3 (0..767)
    int j = threadIdx.x;     // column (0..255)

    if (i < 512) {
        g_W3[i * 256 + j] = Wqkv[i * 256 + j];
        if (j == 0) {
            g_b3[i] = (i < 256) ? bqkv[i] : (bqkv[i] + bh[i - 256]);
        }
    } else {
        int io = i - 512;
        ws[j] = Wout[io * 256 + j];
        __syncthreads();
        float acc = 0.f;
        #pragma unroll 8
        for (int k = 0; k < 256; ++k)
            acc = fmaf(ws[k], Wqkv[(512 + k) * 256 + j], acc);
        g_W3[i * 256 + j] = acc;
        if (j == 0) {
            float b = 0.f;
            for (int k = 0; k < 256; ++k)
                b = fmaf(ws[k], bqkv[512 + k], b);
            g_b3[i] = b;
        }
    }
}

// ---------------------------------------------------------------------------
// Kernel 2: Y = gather(X) @ W3^T + b3
//   A rows are gathered from x (b,c,l,d) in (b*l, c) order; K-contiguous.
//   Tile: 128(M) x 64(N) x 32(K), 256 threads, 8x4 microtile per thread.
// ---------------------------------------------------------------------------
__global__ __launch_bounds__(256) void gemm_kernel(const float* __restrict__ x) {
    __shared__ float As[32][128];
    __shared__ float Bs[32][64];

    const int tid = threadIdx.x;
    const int bm = blockIdx.x;   // 512 tiles
    const int bn = blockIdx.y;   // 12 tiles

    // --- A load mapping: thread -> (row am, k-halfchunk) ---
    const int am = tid & 127;
    const int ak = (tid >> 7) << 4;          // 0 or 16
    const int arow = bm * 128 + am;
    // row r = (b*512 + l)*16 + c ; x offset = ((b*16+c)*512 + l)*256
    const int ci = arow & 15;
    const int t2 = arow >> 4;
    const int li = t2 & 511;
    const int bi = t2 >> 9;
    const float* arow_ptr = x + (size_t)(((bi * 16 + ci) * 512) + li) * 256;

    // --- B load mapping ---
    const int bnn = tid & 63;
    const int bk = (tid >> 6) << 3;          // 0,8,16,24
    const float* brow_ptr = g_W3 + (size_t)(bn * 64 + bnn) * 256;

    float acc[8][4];
    #pragma unroll
    for (int i = 0; i < 8; ++i)
        #pragma unroll
        for (int j = 0; j < 4; ++j) acc[i][j] = 0.f;

    const int tm = (tid & 15) << 2;          // 0..60
    const int tn = (tid >> 4) << 2;          // 0..60

    for (int k0 = 0; k0 < Kdim; k0 += 32) {
        // Load A tile (transposed into As[k][m])
        #pragma unroll
        for (int q = 0; q < 4; ++q) {
            float4 v = *(const float4*)(arow_ptr + k0 + ak + 4 * q);
            As[ak + 4 * q + 0][am] = v.x;
            As[ak + 4 * q + 1][am] = v.y;
            As[ak + 4 * q + 2][am] = v.z;
            As[ak + 4 * q + 3][am] = v.w;
        }
        // Load B tile (transposed into Bs[k][n])
        #pragma unroll
        for (int q = 0; q < 2; ++q) {
            float4 v = *(const float4*)(brow_ptr + k0 + bk + 4 * q);
            Bs[bk + 4 * q + 0][bnn] = v.x;
            Bs[bk + 4 * q + 1][bnn] = v.y;
            Bs[bk + 4 * q + 2][bnn] = v.z;
            Bs[bk + 4 * q + 3][bnn] = v.w;
        }
        __syncthreads();

        #pragma unroll
        for (int k = 0; k < 32; ++k) {
            float4 a0 = *(const float4*)&As[k][tm];
            float4 a1 = *(const float4*)&As[k][tm + 64];
            float4 bv = *(const float4*)&Bs[k][tn];
            float a[8] = {a0.x, a0.y, a0.z, a0.w, a1.x, a1.y, a1.z, a1.w};
            float bb[4] = {bv.x, bv.y, bv.z, bv.w};
            #pragma unroll
            for (int i = 0; i < 8; ++i)
                #pragma unroll
                for (int j = 0; j < 4; ++j)
                    acc[i][j] = fmaf(a[i], bb[j], acc[i][j]);
        }
        __syncthreads();
    }

    // Epilogue: add bias, store
    const int col = bn * 64 + tn;
    const float4 bias = *(const float4*)(g_b3 + col);
    #pragma unroll
    for (int i = 0; i < 8; ++i) {
        int m = (i < 4) ? (tm + i) : (64 + tm + (i - 4));
        size_t r = (size_t)(bm * 128 + m);
        float4 o;
        o.x = acc[i][0] + bias.x;
        o.y = acc[i][1] + bias.y;
        o.z = acc[i][2] + bias.z;
        o.w = acc[i][3] + bias.w;
        *(float4*)(g_Y + r * Ncols + col) = o;
    }
}

// ---------------------------------------------------------------------------
// Kernel 3: per-group additive attention (diag softmax) + scaled output.
//   One CTA per (b,l) group. 256 threads = 16x16 (i,j) score pairs.
// ---------------------------------------------------------------------------
__global__ __launch_bounds__(256) void attn_kernel(const float* __restrict__ Vw,
                                                   const float* __restrict__ bout,
                                                   float* __restrict__ out) {
    __shared__ float qs[16][260];
    __shared__ float ks[16][260];
    __shared__ float Vws[256];
    __shared__ float bouts[256];
    __shared__ float sc[256];
    __shared__ float sdiag[16];

    const int g = blockIdx.x;        // group (b*512 + l)
    const int tid = threadIdx.x;

    // Load q, k' tiles (16 x 256 each) + small vectors
    #pragma unroll
    for (int p = 0; p < 16; ++p) {
        int idx = p * 256 + tid;
        int c = idx >> 8;
        int d = idx & 255;
        size_t row = (size_t)(g * 16 + c);
        qs[c][d] = g_Y[row * Ncols + d];
        ks[c][d] = g_Y[row * Ncols + 256 + d];
    }
    Vws[tid] = Vw[tid];
    bouts[tid] = bout[tid];
    __syncthreads();

    // score[i][j] = sum_d Vw[d] * tanh(q[i,d] + k'[j,d])
    const int i = tid >> 4;
    const int j = tid & 15;
    float accs = 0.f;
    #pragma unroll 4
    for (int d = 0; d < 256; d += 4) {
        float4 a = *(const float4*)&qs[i][d];
        float4 b = *(const float4*)&ks[j][d];
        accs = fmaf(Vws[d + 0], fast_tanh(a.x + b.x), accs);
        accs = fmaf(Vws[d + 1], fast_tanh(a.y + b.y), accs);
        accs = fmaf(Vws[d + 2], fast_tanh(a.z + b.z), accs);
        accs = fmaf(Vws[d + 3], fast_tanh(a.w + b.w), accs);
    }
    sc[i * 16 + j] = accs;   // (+Vb+ba constant cancels in softmax)
    __syncthreads();

    // diag softmax coefficient per row
    if (tid < 16) {
        float m = sc[tid * 16];
        #pragma unroll
        for (int jj = 1; jj < 16; ++jj) m = fmaxf(m, sc[tid * 16 + jj]);
        float sum = 0.f;
        #pragma unroll
        for (int jj = 0; jj < 16; ++jj) sum += __expf(sc[tid * 16 + jj] - m);
        sdiag[tid] = __expf(sc[tid * 16 + tid] - m) / sum;
    }
    __syncthreads();

    // out[b, c, l, :] = s[c] * u[c, :] + bout    (u = third 256 chunk of Y)
    const int li = g & 511;
    const int bi = g >> 9;
    #pragma unroll
    for (int c = 0; c < 16; ++c) {
        float s = sdiag[c];
        size_t row = (size_t)(g * 16 + c);
        size_t o = ((size_t)((bi * 16 + c) * 512) + li) * 256;
        out[o + tid] = fmaf(s, g_Y[row * Ncols + 512 + tid], bouts[tid]);
    }
}

// ---------------------------------------------------------------------------
extern "C" void kernel_launch(void* const* d_in, const int* in_sizes, int n_in,
                              void* d_out, int out_size) {
    const float* x    = (const float*)d_in[0];
    const float* Wqkv = (const float*)d_in[1];
    const float* bqkv = (const float*)d_in[2];
    const float* Vw   = (const float*)d_in[3];
    // d_in[4] = Vb, d_in[6] = ba: uniform additive constants, cancel in softmax
    const float* bh   = (const float*)d_in[5];
    const float* Wout = (const float*)d_in[7];
    const float* bout = (const float*)d_in[8];
    float* out = (float*)d_out;

    prep_kernel<<<Ncols, 256>>>(Wqkv, bqkv, bh, Wout);
    gemm_kernel<<<dim3(Mrows / 128, Ncols / 64), 256>>>(x);
    attn_kernel<<<Bn * Ln, 256>>>(Vw, bout, out);
}

// round 4
// speedup vs baseline: 2.3916x; 2.3916x over previous
#include <cuda_runtime.h>
#include <cuda_bf16.h>
#include <cstdint>

// Problem constants
#define Bn 8
#define Cn 16
#define Ln 512
#define Dn 256
#define Mrows 65536
#define Ncols 768
#define Kdim 256

// Scratch (device globals; no runtime allocation allowed)
__device__ __align__(16) __nv_bfloat16 g_Ahi[(size_t)Mrows * Kdim];  // 32 MB
__device__ __align__(16) __nv_bfloat16 g_Alo[(size_t)Mrows * Kdim];  // 32 MB
__device__ __align__(16) __nv_bfloat16 g_Bhi[Ncols * Kdim];
__device__ __align__(16) __nv_bfloat16 g_Blo[Ncols * Kdim];
__device__ float g_b3[Ncols];
__device__ float g_Y[(size_t)Mrows * Ncols];   // 192 MB intermediate

// ---------------------------------------------------------------------------
__device__ __forceinline__ uint32_t smem_u32(const void* p) {
    uint32_t a;
    asm("{ .reg .u64 t; cvta.to.shared.u64 t, %1; cvt.u32.u64 %0, t; }" : "=r"(a) : "l"(p));
    return a;
}
__device__ __forceinline__ float fast_tanh(float x) {
    float y; asm("tanh.approx.f32 %0, %1;" : "=f"(y) : "f"(x)); return y;
}
__device__ __forceinline__ uint32_t swz128(uint32_t off) {
    return off ^ ((off >> 3) & 0x70);
}
// packed bf16x2: lo16 = a, hi16 = b
__device__ __forceinline__ uint32_t cvt_bf2(float a, float b) {
    uint32_t r;
    asm("cvt.rn.satfinite.bf16x2.f32 %0, %1, %2;" : "=r"(r) : "f"(b), "f"(a));
    return r;
}
__device__ __forceinline__ void ldsm4(uint32_t* r, uint32_t addr) {
    asm volatile("ldmatrix.sync.aligned.m8n8.x4.shared.b16 {%0,%1,%2,%3}, [%4];"
        : "=r"(r[0]), "=r"(r[1]), "=r"(r[2]), "=r"(r[3]) : "r"(addr));
}
__device__ __forceinline__ void mma16816(float* d, const uint32_t* a, uint32_t b0, uint32_t b1) {
    asm volatile("mma.sync.aligned.m16n8k16.row.col.f32.bf16.bf16.f32 "
        "{%0,%1,%2,%3}, {%4,%5,%6,%7}, {%8,%9}, {%0,%1,%2,%3};"
        : "+f"(d[0]), "+f"(d[1]), "+f"(d[2]), "+f"(d[3])
        : "r"(a[0]), "r"(a[1]), "r"(a[2]), "r"(a[3]), "r"(b0), "r"(b1));
}

// ---------------------------------------------------------------------------
// Kernel 1: build combined weights, split to bf16 hi/lo.
//   rows [0,256): Wq | [256,512): Wk (+bh in bias) | [512,768): Wout@Wv
// ---------------------------------------------------------------------------
__global__ void prep_kernel(const float* __restrict__ Wqkv,
                            const float* __restrict__ bqkv,
                            const float* __restrict__ bh,
                            const float* __restrict__ Wout) {
    __shared__ float ws[256];
    int i = blockIdx.x;
    int j = threadIdx.x;
    float val;
    if (i < 512) {
        val = Wqkv[i * 256 + j];
        if (j == 0) g_b3[i] = (i < 256) ? bqkv[i] : (bqkv[i] + bh[i - 256]);
    } else {
        int io = i - 512;
        ws[j] = Wout[io * 256 + j];
        __syncthreads();
        float a0 = 0.f, a1 = 0.f, a2 = 0.f, a3 = 0.f;
        #pragma unroll 4
        for (int k = 0; k < 256; k += 4) {
            a0 = fmaf(ws[k + 0], Wqkv[(512 + k + 0) * 256 + j], a0);
            a1 = fmaf(ws[k + 1], Wqkv[(512 + k + 1) * 256 + j], a1);
            a2 = fmaf(ws[k + 2], Wqkv[(512 + k + 2) * 256 + j], a2);
            a3 = fmaf(ws[k + 3], Wqkv[(512 + k + 3) * 256 + j], a3);
        }
        val = (a0 + a1) + (a2 + a3);
        if (j == 0) {
            float b = 0.f;
            for (int k = 0; k < 256; ++k) b = fmaf(ws[k], bqkv[512 + k], b);
            g_b3[i] = b;
        }
    }
    __nv_bfloat16 h = __float2bfloat16(val);
    g_Bhi[i * 256 + j] = h;
    g_Blo[i * 256 + j] = __float2bfloat16(val - __bfloat162float(h));
}

// ---------------------------------------------------------------------------
// Kernel 1b: gather-transpose x -> A rows (b*l, c) and split fp32 -> bf16 hi/lo.
//   One thread per 4 consecutive d-elements; reads & writes fully coalesced.
// ---------------------------------------------------------------------------
__global__ __launch_bounds__(256) void split_x_kernel(const float* __restrict__ x) {
    size_t i4 = ((size_t)blockIdx.x * 256 + threadIdx.x) * 4;  // x linear idx
    float4 v = *(const float4*)(x + i4);
    int d = (int)(i4 & 255);
    size_t t = i4 >> 8;
    int l = (int)(t & 511); t >>= 9;
    int c = (int)(t & 15);
    int b = (int)(t >> 4);
    size_t r = ((size_t)(b * 512 + l) * 16 + c);
    uint32_t h0 = cvt_bf2(v.x, v.y);
    uint32_t h1 = cvt_bf2(v.z, v.w);
    uint32_t l0 = cvt_bf2(v.x - __uint_as_float(h0 << 16), v.y - __uint_as_float(h0 & 0xffff0000u));
    uint32_t l1 = cvt_bf2(v.z - __uint_as_float(h1 << 16), v.w - __uint_as_float(h1 & 0xffff0000u));
    *(uint2*)(g_Ahi + r * 256 + d) = make_uint2(h0, h1);
    *(uint2*)(g_Alo + r * 256 + d) = make_uint2(l0, l1);
}

// ---------------------------------------------------------------------------
// Kernel 2: bf16-split GEMM via mma.sync (m16n8k16), fp32 accumulate.
//   Y = A @ W3^T + b3.  CTA tile 128x64, K-chunk 64, 8 warps (4M x 2N),
//   warp tile 32x32. D = Ahi*Bhi + Ahi*Blo + Alo*Bhi.
// ---------------------------------------------------------------------------
__global__ __launch_bounds__(256) void gemm_mma_kernel() {
    __shared__ __align__(16) __nv_bfloat16 sAhi[128 * 64];
    __shared__ __align__(16) __nv_bfloat16 sAlo[128 * 64];
    __shared__ __align__(16) __nv_bfloat16 sBhi[64 * 64];
    __shared__ __align__(16) __nv_bfloat16 sBlo[64 * 64];

    const int tid = threadIdx.x;
    const int lane = tid & 31;
    const int wid = tid >> 5;
    const int wm = (wid & 3) * 32;       // warp M offset
    const int wn = (wid >> 2) * 32;      // warp N offset
    const int nt0 = blockIdx.x * 64;     // N tile base (fastest -> L2-friendly)
    const int mt0 = blockIdx.y * 128;

    // --- SMEM fill mappings (16B granules) ---
    size_t a_src[4]; uint32_t a_dst[4];
    #pragma unroll
    for (int t = 0; t < 4; ++t) {
        int idx = tid + t * 256;
        int r = idx >> 3, g = idx & 7;
        a_src[t] = (size_t)(mt0 + r) * 256 + g * 8;
        a_dst[t] = swz128((uint32_t)(r * 128 + g * 16));
    }
    size_t b_src[2]; uint32_t b_dst[2];
    #pragma unroll
    for (int t = 0; t < 2; ++t) {
        int idx = tid + t * 256;
        int r = idx >> 3, g = idx & 7;
        b_src[t] = (size_t)(nt0 + r) * 256 + g * 8;
        b_dst[t] = swz128((uint32_t)(r * 128 + g * 16));
    }

    // --- ldmatrix lane address components (unswizzled) ---
    const int lrow_a = lane & 15;
    const int lk_a = (lane >> 4) * 16;                    // byte offset within k16
    const int lrow_b = (lane & 7) + ((lane >> 4) << 3);
    const int lk_b = ((lane >> 3) & 1) * 16;

    const uint32_t sAhi_b = smem_u32(sAhi), sAlo_b = smem_u32(sAlo);
    const uint32_t sBhi_b = smem_u32(sBhi), sBlo_b = smem_u32(sBlo);

    // precompute per-mt / per-np unswizzled bases
    uint32_t aoff[2], boff[2];
    #pragma unroll
    for (int mt = 0; mt < 2; ++mt) aoff[mt] = (uint32_t)((wm + mt * 16 + lrow_a) * 128 + lk_a);
    #pragma unroll
    for (int np = 0; np < 2; ++np) boff[np] = (uint32_t)((wn + np * 16 + lrow_b) * 128 + lk_b);

    float acc[2][4][4];
    #pragma unroll
    for (int mt = 0; mt < 2; ++mt)
        #pragma unroll
        for (int nt = 0; nt < 4; ++nt)
            #pragma unroll
            for (int q = 0; q < 4; ++q) acc[mt][nt][q] = 0.f;

    for (int kc = 0; kc < 4; ++kc) {
        const int ko = kc * 64;
        __syncthreads();
        #pragma unroll
        for (int t = 0; t < 4; ++t) {
            *(uint4*)((char*)sAhi + a_dst[t]) = *(const uint4*)(g_Ahi + a_src[t] + ko);
            *(uint4*)((char*)sAlo + a_dst[t]) = *(const uint4*)(g_Alo + a_src[t] + ko);
        }
        #pragma unroll
        for (int t = 0; t < 2; ++t) {
            *(uint4*)((char*)sBhi + b_dst[t]) = *(const uint4*)(g_Bhi + b_src[t] + ko);
            *(uint4*)((char*)sBlo + b_dst[t]) = *(const uint4*)(g_Blo + b_src[t] + ko);
        }
        __syncthreads();

        #pragma unroll
        for (int kk = 0; kk < 4; ++kk) {
            const uint32_t kb = kk * 32;
            uint32_t ahi[2][4], alo[2][4], bhi[2][4], blo[2][4];
            #pragma unroll
            for (int mt = 0; mt < 2; ++mt) {
                uint32_t off = swz128(aoff[mt] + kb);
                ldsm4(ahi[mt], sAhi_b + off);
                ldsm4(alo[mt], sAlo_b + off);
            }
            #pragma unroll
            for (int np = 0; np < 2; ++np) {
                uint32_t off = swz128(boff[np] + kb);
                ldsm4(bhi[np], sBhi_b + off);
                ldsm4(blo[np], sBlo_b + off);
            }
            #pragma unroll
            for (int mt = 0; mt < 2; ++mt) {
                #pragma unroll
                for (int nt = 0; nt < 4; ++nt) {
                    const int np = nt >> 1, s = (nt & 1) * 2;
                    mma16816(acc[mt][nt], ahi[mt], bhi[np][s], bhi[np][s + 1]);
                    mma16816(acc[mt][nt], ahi[mt], blo[np][s], blo[np][s + 1]);
                    mma16816(acc[mt][nt], alo[mt], bhi[np][s], bhi[np][s + 1]);
                }
            }
        }
    }

    // Epilogue: add bias, store fp32 to g_Y
    const int g4 = lane >> 2, tq = lane & 3;
    #pragma unroll
    for (int mt = 0; mt < 2; ++mt) {
        #pragma unroll
        for (int nt = 0; nt < 4; ++nt) {
            const int col = nt0 + wn + nt * 8 + tq * 2;
            const float2 bb = *(const float2*)(g_b3 + col);
            const int row0 = mt0 + wm + mt * 16 + g4;
            float2 o0, o1;
            o0.x = acc[mt][nt][0] + bb.x;  o0.y = acc[mt][nt][1] + bb.y;
            o1.x = acc[mt][nt][2] + bb.x;  o1.y = acc[mt][nt][3] + bb.y;
            *(float2*)(g_Y + (size_t)row0 * Ncols + col) = o0;
            *(float2*)(g_Y + (size_t)(row0 + 8) * Ncols + col) = o1;
        }
    }
}

// ---------------------------------------------------------------------------
// Kernel 3: per-group additive attention (diag softmax) + scaled output.
// ---------------------------------------------------------------------------
__global__ __launch_bounds__(256) void attn_kernel(const float* __restrict__ Vw,
                                                   const float* __restrict__ bout,
                                                   float* __restrict__ out) {
    __shared__ float qs[16][260];
    __shared__ float ks[16][260];
    __shared__ float Vws[256];
    __shared__ float bouts[256];
    __shared__ float sc[256];
    __shared__ float sdiag[16];

    const int g = blockIdx.x;
    const int tid = threadIdx.x;

    #pragma unroll
    for (int p = 0; p < 16; ++p) {
        int idx = p * 256 + tid;
        int c = idx >> 8;
        int d = idx & 255;
        size_t row = (size_t)(g * 16 + c);
        qs[c][d] = g_Y[row * Ncols + d];
        ks[c][d] = g_Y[row * Ncols + 256 + d];
    }
    Vws[tid] = Vw[tid];
    bouts[tid] = bout[tid];
    __syncthreads();

    const int i = tid >> 4;
    const int j = tid & 15;
    float accs = 0.f;
    #pragma unroll 4
    for (int d = 0; d < 256; d += 4) {
        float4 a = *(const float4*)&qs[i][d];
        float4 b = *(const float4*)&ks[j][d];
        accs = fmaf(Vws[d + 0], fast_tanh(a.x + b.x), accs);
        accs = fmaf(Vws[d + 1], fast_tanh(a.y + b.y), accs);
        accs = fmaf(Vws[d + 2], fast_tanh(a.z + b.z), accs);
        accs = fmaf(Vws[d + 3], fast_tanh(a.w + b.w), accs);
    }
    sc[i * 16 + j] = accs;
    __syncthreads();

    if (tid < 16) {
        float m = sc[tid * 16];
        #pragma unroll
        for (int jj = 1; jj < 16; ++jj) m = fmaxf(m, sc[tid * 16 + jj]);
        float sum = 0.f;
        #pragma unroll
        for (int jj = 0; jj < 16; ++jj) sum += __expf(sc[tid * 16 + jj] - m);
        sdiag[tid] = __expf(sc[tid * 16 + tid] - m) / sum;
    }
    __syncthreads();

    const int li = g & 511;
    const int bi = g >> 9;
    #pragma unroll
    for (int c = 0; c < 16; ++c) {
        float s = sdiag[c];
        size_t row = (size_t)(g * 16 + c);
        size_t o = ((size_t)((bi * 16 + c) * 512) + li) * 256;
        out[o + tid] = fmaf(s, g_Y[row * Ncols + 512 + tid], bouts[tid]);
    }
}

// ---------------------------------------------------------------------------
extern "C" void kernel_launch(void* const* d_in, const int* in_sizes, int n_in,
                              void* d_out, int out_size) {
    const float* x    = (const float*)d_in[0];
    const float* Wqkv = (const float*)d_in[1];
    const float* bqkv = (const float*)d_in[2];
    const float* Vw   = (const float*)d_in[3];
    // d_in[4] = Vb, d_in[6] = ba: uniform additive constants, cancel in softmax
    const float* bh   = (const float*)d_in[5];
    const float* Wout = (const float*)d_in[7];
    const float* bout = (const float*)d_in[8];
    float* out = (float*)d_out;

    prep_kernel<<<Ncols, 256>>>(Wqkv, bqkv, bh, Wout);
    split_x_kernel<<<(Mrows * Kdim) / (256 * 4), 256>>>(x);
    gemm_mma_kernel<<<dim3(Ncols / 64, Mrows / 128), 256>>>();
    attn_kernel<<<Bn * Ln, 256>>>(Vw, bout, out);
}